// round 5
// baseline (speedup 1.0000x reference)
#include <cuda_runtime.h>

#define C      128
#define MAX_N  100000
#define MAX_E  1600000

// Scratch (allocation-free rule: __device__ globals)
__device__ int   g_is64;
__device__ int   g_ei[2 * MAX_E];           // normalized int32 edge index
__device__ int   g_deg[MAX_N];
__device__ float g_dinv[MAX_N];
__device__ float g_hs[(size_t)MAX_N * C];   // hs = dinv[row] * (x @ W)[row]

// ---------------------------------------------------------------------------
// 0a) dtype detect: int64 values < 2^31 have zero odd 32-bit words (LE).
__global__ void k_detect(const unsigned* __restrict__ ei32) {
    int all0 = 1;
#pragma unroll 4
    for (int i = 0; i < 64; i++)
        if (ei32[2 * i + 1] != 0u) all0 = 0;
    g_is64 = all0;
}

// 0b) normalize edge index to int32
__global__ void k_convert(const void* __restrict__ ei, int total) {
    int i = blockIdx.x * blockDim.x + threadIdx.x;
    if (i >= total) return;
    int v;
    if (g_is64) v = (int)((const long long*)ei)[i];
    else        v = ((const int*)ei)[i];
    g_ei[i] = v;
}

// ---------------------------------------------------------------------------
// 1) degree init to 1 (self loop)
__global__ void k_init_deg(int n) {
    int i = blockIdx.x * blockDim.x + threadIdx.x;
    if (i < n) g_deg[i] = 1;
}

// 2) in-degree count over edge targets (col)
__global__ void k_count(int E, int n) {
    int i = blockIdx.x * blockDim.x + threadIdx.x;
    if (i >= E) return;
    unsigned c = (unsigned)g_ei[E + i];
    if (c < (unsigned)n) atomicAdd(&g_deg[c], 1);
}

// 3) dinv = rsqrt(deg)   (deg >= 1 always due to self loop)
__global__ void k_dinv(int n) {
    int i = blockIdx.x * blockDim.x + threadIdx.x;
    if (i < n) g_dinv[i] = rsqrtf((float)g_deg[i]);
}

// ---------------------------------------------------------------------------
// 4) GEMM: hs[row] = dinv[row] * (x[row] @ W); also seed out[row] = hs[row]
//    (folds the self-loop contribution: final kernel multiplies by dinv[col]).
//    Block: 128 threads (thread t = output col), 32 rows per block.
#define GM_ROWS 32
__global__ void __launch_bounds__(128) k_gemm(
    const float* __restrict__ x, const float* __restrict__ W,
    float* __restrict__ out, int n)
{
    __shared__ float4 xs[GM_ROWS][C / 4];   // 16 KB x-tile
    const int t    = threadIdx.x;           // 0..127 = output channel
    const int base = blockIdx.x * GM_ROWS;
    const int rows = min(GM_ROWS, n - base);

    // cooperative coalesced load of the x tile
    const float4* xg = (const float4*)(x + (size_t)base * C);
    for (int i = t; i < rows * (C / 4); i += 128)
        ((float4*)xs)[i] = xg[i];
    __syncthreads();

    float acc[GM_ROWS];
#pragma unroll
    for (int r = 0; r < GM_ROWS; r++) acc[r] = 0.0f;

    // k-loop in chunks of 4: 4 coalesced W loads + 1 broadcast LDS.128 per row
    for (int k = 0; k < C; k += 4) {
        float w0 = W[(k + 0) * C + t];
        float w1 = W[(k + 1) * C + t];
        float w2 = W[(k + 2) * C + t];
        float w3 = W[(k + 3) * C + t];
#pragma unroll
        for (int r = 0; r < GM_ROWS; r++) {
            float4 xv = xs[r][k >> 2];
            acc[r] = fmaf(xv.x, w0, acc[r]);
            acc[r] = fmaf(xv.y, w1, acc[r]);
            acc[r] = fmaf(xv.z, w2, acc[r]);
            acc[r] = fmaf(xv.w, w3, acc[r]);
        }
    }

    for (int r = 0; r < rows; r++) {
        int row = base + r;
        float v = acc[r] * g_dinv[row];
        g_hs[(size_t)row * C + t] = v;
        out [(size_t)row * C + t] = v;   // self-loop seed
    }
}

// ---------------------------------------------------------------------------
// 5) edge scatter: one warp per edge; lane l handles channels [4l, 4l+4).
//    out[col] += hs[row]  via vector reduction (red.global.add.v4.f32).
__global__ void __launch_bounds__(256) k_scatter(
    int E, int n, float* __restrict__ out)
{
    int warp = (blockIdx.x * blockDim.x + threadIdx.x) >> 5;
    if (warp >= E) return;
    int lane = threadIdx.x & 31;

    unsigned row = (unsigned)g_ei[warp];        // uniform across warp
    unsigned col = (unsigned)g_ei[E + warp];
    if (row >= (unsigned)n || col >= (unsigned)n) return;  // insurance

    float4 v = *(const float4*)(g_hs + (size_t)row * C + lane * 4);
    float* dst = out + (size_t)col * C + lane * 4;
    asm volatile("red.global.add.v4.f32 [%0], {%1,%2,%3,%4};"
                 :: "l"(dst), "f"(v.x), "f"(v.y), "f"(v.z), "f"(v.w)
                 : "memory");
}

// ---------------------------------------------------------------------------
// 6) finalize: out = relu(dinv[col] * agg + b)
__global__ void k_final(float* __restrict__ out, const float* __restrict__ b, int n) {
    int idx = blockIdx.x * blockDim.x + threadIdx.x;   // over n * 32 float4
    if (idx >= n * (C / 4)) return;
    int row = idx >> 5;        // C/4 == 32
    int c4  = idx & 31;
    float d  = g_dinv[row];
    float4 v = ((float4*)out)[idx];
    float4 bb = ((const float4*)b)[c4];
    v.x = fmaxf(fmaf(v.x, d, bb.x), 0.0f);
    v.y = fmaxf(fmaf(v.y, d, bb.y), 0.0f);
    v.z = fmaxf(fmaf(v.z, d, bb.z), 0.0f);
    v.w = fmaxf(fmaf(v.w, d, bb.w), 0.0f);
    ((float4*)out)[idx] = v;
}

// ---------------------------------------------------------------------------
extern "C" void kernel_launch(void* const* d_in, const int* in_sizes, int n_in,
                              void* d_out, int out_size)
{
    const float* x  = (const float*)d_in[0];
    const void*  ei = d_in[1];                 // [2, E] int32 or int64 (detected)
    const float* W  = (const float*)d_in[2];
    const float* b  = (const float*)d_in[3];
    float*       out = (float*)d_out;

    const int n = in_sizes[0] / C;
    const int E = in_sizes[1] / 2;

    k_detect  <<<1, 1>>>((const unsigned*)ei);
    k_convert <<<(2 * E + 255) / 256, 256>>>(ei, 2 * E);
    k_init_deg<<<(n + 255) / 256, 256>>>(n);
    k_count   <<<(E + 255) / 256, 256>>>(E, n);
    k_dinv    <<<(n + 255) / 256, 256>>>(n);
    k_gemm    <<<(n + GM_ROWS - 1) / GM_ROWS, 128>>>(x, W, out, n);
    k_scatter <<<(E + 7) / 8, 256>>>(E, n, out);
    k_final   <<<(n * (C / 4) + 255) / 256, 256>>>(out, b, n);
}

// round 6
// speedup vs baseline: 1.0452x; 1.0452x over previous
#include <cuda_runtime.h>

#define C      128
#define MAX_N  100000
#define MAX_E  1600000

// Scratch (allocation-free rule: __device__ globals)
__device__ int   g_is64;
__device__ int   g_ei[2 * MAX_E];            // normalized int32 edge index
__device__ int   g_deg[MAX_N];               // edge-only in-degree (no self loop)
__device__ int   g_off[MAX_N];               // CSR start offsets (by target)
__device__ int   g_cur[MAX_N];               // fill cursors
__device__ int   g_csr[MAX_E];               // source node per CSR slot
__device__ float g_dinv[MAX_N];              // rsqrt(deg+1)
__device__ float g_hs[(size_t)MAX_N * C];    // hs = dinv[row] * (x @ W)[row]
__device__ unsigned long long g_wt[64 * C];  // W as k-pair f32x2: (W[2k2][c], W[2k2+1][c])

// ---------------------------------------------------------------------------
// 0a) dtype detect: int64 values < 2^31 have zero odd 32-bit words (LE).
__global__ void k_detect(const unsigned* __restrict__ ei32) {
    int all0 = 1;
#pragma unroll 4
    for (int i = 0; i < 64; i++)
        if (ei32[2 * i + 1] != 0u) all0 = 0;
    g_is64 = all0;
}

// 0b) zero degrees
__global__ void k_zero(int n) {
    int i = blockIdx.x * blockDim.x + threadIdx.x;
    if (i < n) g_deg[i] = 0;
}

// 1) normalize edge index to int32 AND count in-degree (col half) in one pass
__global__ void k_convert_count(const void* __restrict__ ei, int E, int n) {
    int i = blockIdx.x * blockDim.x + threadIdx.x;
    if (i >= 2 * E) return;
    int v;
    if (g_is64) v = (int)((const long long*)ei)[i];
    else        v = ((const int*)ei)[i];
    g_ei[i] = v;
    if (i >= E && (unsigned)v < (unsigned)n) atomicAdd(&g_deg[v], 1);
}

// 2) single-block exclusive scan over degrees -> CSR offsets + cursors + dinv
__global__ void __launch_bounds__(1024) k_scan(int n) {
    __shared__ int part[1024];
    const int tid   = threadIdx.x;
    const int chunk = (n + 1023) >> 10;
    const int beg   = tid * chunk;
    const int end   = min(beg + chunk, n);

    int s = 0;
    for (int i = beg; i < end; i++) s += g_deg[i];
    part[tid] = s;
    __syncthreads();
    for (int off = 1; off < 1024; off <<= 1) {       // Hillis-Steele inclusive
        int v = (tid >= off) ? part[tid - off] : 0;
        __syncthreads();
        part[tid] += v;
        __syncthreads();
    }
    int run = tid ? part[tid - 1] : 0;
    for (int i = beg; i < end; i++) {
        int d = g_deg[i];
        g_off[i]  = run;
        g_cur[i]  = run;
        g_dinv[i] = rsqrtf((float)(d + 1));           // +1 = self loop
        run += d;
    }
}

// 3) CSR fill: slot per edge via cursor atomics; store source node
__global__ void k_fill(int E, int n) {
    int i = blockIdx.x * blockDim.x + threadIdx.x;
    if (i >= E) return;
    unsigned row = (unsigned)g_ei[i];
    unsigned col = (unsigned)g_ei[E + i];
    if (row >= (unsigned)n || col >= (unsigned)n) return;
    int slot = atomicAdd(&g_cur[col], 1);
    g_csr[slot] = (int)row;
}

// 4) pre-pack W into k-pair f32x2 layout: g_wt[k2*C + c] = (W[2k2][c], W[2k2+1][c])
__global__ void k_wt(const float* __restrict__ W) {
    int i = blockIdx.x * blockDim.x + threadIdx.x;
    if (i >= 64 * C) return;
    int c = i & (C - 1), k2 = i >> 7;
    unsigned lo = __float_as_uint(W[(2 * k2)     * C + c]);
    unsigned hi = __float_as_uint(W[(2 * k2 + 1) * C + c]);
    g_wt[i] = ((unsigned long long)hi << 32) | lo;
}

// ---------------------------------------------------------------------------
// 5) GEMM via packed fma.rn.f32x2: hs[row] = dinv[row] * (x[row] @ W).
//    Thread t = channel t; 32 rows per block. x-tile in shared as ulonglong2:
//    each 16B holds 2 pre-packed (k,k+1) f32x2 pairs -> zero pack instructions.
//    acc.lo sums even-k products, acc.hi odd-k; added in epilogue (exact fp32).
#define GM_ROWS 32
__global__ void __launch_bounds__(128) k_gemm(const float* __restrict__ x, int n) {
    __shared__ ulonglong2 xs[GM_ROWS][C / 4];   // 16 KB
    const int t    = threadIdx.x;
    const int base = blockIdx.x * GM_ROWS;
    const int rows = min(GM_ROWS, n - base);

    const ulonglong2* xg = (const ulonglong2*)(x + (size_t)base * C);
    for (int i = t; i < rows * (C / 4); i += 128)
        ((ulonglong2*)xs)[i] = xg[i];
    __syncthreads();

    unsigned long long acc[GM_ROWS];
#pragma unroll
    for (int r = 0; r < GM_ROWS; r++) acc[r] = 0ull;

#pragma unroll 4
    for (int k4 = 0; k4 < C / 4; k4++) {          // k4 covers k-steps 4k4..4k4+3
        unsigned long long wA = g_wt[(2 * k4)     * C + t];
        unsigned long long wB = g_wt[(2 * k4 + 1) * C + t];
#pragma unroll
        for (int r = 0; r < GM_ROWS; r++) {
            ulonglong2 xv = xs[r][k4];            // broadcast LDS.128
            asm("fma.rn.f32x2 %0, %1, %2, %0;" : "+l"(acc[r]) : "l"(xv.x), "l"(wA));
            asm("fma.rn.f32x2 %0, %1, %2, %0;" : "+l"(acc[r]) : "l"(xv.y), "l"(wB));
        }
    }

    for (int r = 0; r < rows; r++) {
        int row  = base + r;
        float lo = __uint_as_float((unsigned)(acc[r] & 0xffffffffull));
        float hi = __uint_as_float((unsigned)(acc[r] >> 32));
        g_hs[(size_t)row * C + t] = (lo + hi) * g_dinv[row];
    }
}

// ---------------------------------------------------------------------------
// 6) gather-reduce + finalize (fused): one warp per destination node.
//    lane l owns channels [4l, 4l+4). acc seeded with hs[v] (self loop).
//    out[v] = relu(dinv[v] * (hs[v] + sum_{neighbors} hs[row]) + b)
__global__ void __launch_bounds__(256) k_agg(float* __restrict__ out,
                                             const float* __restrict__ b, int n) {
    int warp = (blockIdx.x * blockDim.x + threadIdx.x) >> 5;
    if (warp >= n) return;
    const int lane = threadIdx.x & 31;
    const int v    = warp;
    const int beg  = g_off[v];
    const int cnt  = g_deg[v];

    float4 acc = *(const float4*)(g_hs + (size_t)v * C + lane * 4);  // self loop

    for (int base = 0; base < cnt; base += 32) {
        int idx = 0;
        if (base + lane < cnt) idx = g_csr[beg + base + lane];
        int m = min(32, cnt - base);
        for (int j = 0; j < m; j++) {
            int row  = __shfl_sync(0xffffffffu, idx, j);
            float4 h = *(const float4*)(g_hs + (size_t)row * C + lane * 4);
            acc.x += h.x; acc.y += h.y; acc.z += h.z; acc.w += h.w;
        }
    }

    const float  d  = g_dinv[v];
    const float4 bb = ((const float4*)b)[lane];
    float4 o;
    o.x = fmaxf(fmaf(acc.x, d, bb.x), 0.0f);
    o.y = fmaxf(fmaf(acc.y, d, bb.y), 0.0f);
    o.z = fmaxf(fmaf(acc.z, d, bb.z), 0.0f);
    o.w = fmaxf(fmaf(acc.w, d, bb.w), 0.0f);
    ((float4*)out)[(size_t)v * (C / 4) + lane] = o;
}

// ---------------------------------------------------------------------------
extern "C" void kernel_launch(void* const* d_in, const int* in_sizes, int n_in,
                              void* d_out, int out_size)
{
    const float* x  = (const float*)d_in[0];
    const void*  ei = d_in[1];                 // [2, E] int32 or int64 (detected)
    const float* W  = (const float*)d_in[2];
    const float* b  = (const float*)d_in[3];
    float*       out = (float*)d_out;

    const int n = in_sizes[0] / C;
    const int E = in_sizes[1] / 2;

    k_detect       <<<1, 1>>>((const unsigned*)ei);
    k_zero         <<<(n + 255) / 256, 256>>>(n);
    k_convert_count<<<(2 * E + 255) / 256, 256>>>(ei, E, n);
    k_scan         <<<1, 1024>>>(n);
    k_fill         <<<(E + 255) / 256, 256>>>(E, n);
    k_wt           <<<(64 * C + 255) / 256, 256>>>(W);
    k_gemm         <<<(n + GM_ROWS - 1) / GM_ROWS, 128>>>(x, n);
    k_agg          <<<(n * 32 + 255) / 256, 256>>>(out, b, n);
}

// round 9
// speedup vs baseline: 1.8147x; 1.7361x over previous
#include <cuda_runtime.h>

#define C      128
#define MAX_N  100000
#define MAX_E  1600000
#define SCAN_B 256

// Scratch (allocation-free rule: __device__ globals)
__device__ int   g_is64;
__device__ int   g_ei[2 * MAX_E];            // normalized int32 edge index
__device__ int   g_deg[MAX_N];               // edge-only in-degree (no self loop)
__device__ int   g_off[MAX_N];               // CSR start offsets (by target)
__device__ int   g_cur[MAX_N];               // fill cursors
__device__ int   g_csr[MAX_E];               // source node per CSR slot
__device__ int   g_bsum[(MAX_N + SCAN_B - 1) / SCAN_B + 1];  // block sums / prefixes
__device__ float g_dinv[MAX_N];              // rsqrt(deg+1)
__device__ float g_hs[(size_t)MAX_N * C];    // hs = dinv[row] * (x @ W)[row]
__device__ unsigned long long g_wt[64 * C];  // W as k-pair f32x2: (W[2k2][c], W[2k2+1][c])

// ---------------------------------------------------------------------------
// 0a) dtype detect: int64 values < 2^31 have zero odd 32-bit words (LE).
__global__ void k_detect(const unsigned* __restrict__ ei32) {
    int all0 = 1;
#pragma unroll 4
    for (int i = 0; i < 64; i++)
        if (ei32[2 * i + 1] != 0u) all0 = 0;
    g_is64 = all0;
}

// 0b) zero degrees
__global__ void k_zero(int n) {
    int i = blockIdx.x * blockDim.x + threadIdx.x;
    if (i < n) g_deg[i] = 0;
}

// 1) normalize edge index to int32 AND count in-degree (col half) in one pass
__global__ void k_convert_count(const void* __restrict__ ei, int E, int n) {
    int i = blockIdx.x * blockDim.x + threadIdx.x;
    if (i >= 2 * E) return;
    int v;
    if (g_is64) v = (int)((const long long*)ei)[i];
    else        v = ((const int*)ei)[i];
    g_ei[i] = v;
    if (i >= E && (unsigned)v < (unsigned)n) atomicAdd(&g_deg[v], 1);
}

// ---------------------------------------------------------------------------
// 2) multi-block exclusive scan of g_deg -> g_off (3 phases, all chip-wide)

// 2a) block-local scan; g_off gets block-local exclusive prefix, g_bsum block total
__global__ void __launch_bounds__(SCAN_B) k_scan1(int n) {
    __shared__ int sh[SCAN_B];
    const int tid = threadIdx.x;
    const int i   = blockIdx.x * SCAN_B + tid;
    int d = (i < n) ? g_deg[i] : 0;
    sh[tid] = d;
    __syncthreads();
#pragma unroll
    for (int off = 1; off < SCAN_B; off <<= 1) {
        int v = (tid >= off) ? sh[tid - off] : 0;
        __syncthreads();
        sh[tid] += v;
        __syncthreads();
    }
    if (i < n) g_off[i] = sh[tid] - d;            // block-local exclusive
    if (tid == SCAN_B - 1) g_bsum[blockIdx.x] = sh[tid];
}

// 2b) single block scans the block sums (nb <= 1024) -> exclusive prefixes
__global__ void __launch_bounds__(1024) k_scan2(int nb) {
    __shared__ int sh[1024];
    const int tid = threadIdx.x;
    int d = (tid < nb) ? g_bsum[tid] : 0;
    sh[tid] = d;
    __syncthreads();
#pragma unroll
    for (int off = 1; off < 1024; off <<= 1) {
        int v = (tid >= off) ? sh[tid - off] : 0;
        __syncthreads();
        sh[tid] += v;
        __syncthreads();
    }
    if (tid < nb) g_bsum[tid] = sh[tid] - d;      // exclusive block prefix
}

// 2c) add block prefix; emit offsets, cursors, dinv
__global__ void __launch_bounds__(SCAN_B) k_scan3(int n) {
    const int i = blockIdx.x * SCAN_B + threadIdx.x;
    if (i >= n) return;
    int o = g_off[i] + g_bsum[blockIdx.x];
    g_off[i]  = o;
    g_cur[i]  = o;
    g_dinv[i] = rsqrtf((float)(g_deg[i] + 1));    // +1 = self loop
}

// ---------------------------------------------------------------------------
// 3) CSR fill: slot per edge via cursor atomics; store source node
__global__ void k_fill(int E, int n) {
    int i = blockIdx.x * blockDim.x + threadIdx.x;
    if (i >= E) return;
    unsigned row = (unsigned)g_ei[i];
    unsigned col = (unsigned)g_ei[E + i];
    if (row >= (unsigned)n || col >= (unsigned)n) return;
    int slot = atomicAdd(&g_cur[col], 1);
    g_csr[slot] = (int)row;
}

// 4) pre-pack W into k-pair f32x2 layout: g_wt[k2*C + c] = (W[2k2][c], W[2k2+1][c])
__global__ void k_wt(const float* __restrict__ W) {
    int i = blockIdx.x * blockDim.x + threadIdx.x;
    if (i >= 64 * C) return;
    int c = i & (C - 1), k2 = i >> 7;
    unsigned lo = __float_as_uint(W[(2 * k2)     * C + c]);
    unsigned hi = __float_as_uint(W[(2 * k2 + 1) * C + c]);
    g_wt[i] = ((unsigned long long)hi << 32) | lo;
}

// ---------------------------------------------------------------------------
// 5) GEMM via packed fma.rn.f32x2: hs[row] = dinv[row] * (x[row] @ W).
//    Thread t = channel t; 32 rows per block. x-tile in shared as ulonglong2:
//    each 16B holds 2 pre-packed (k,k+1) f32x2 pairs -> zero pack instructions.
//    acc.lo sums even-k products, acc.hi odd-k; added in epilogue (exact fp32).
#define GM_ROWS 32
__global__ void __launch_bounds__(128) k_gemm(const float* __restrict__ x, int n) {
    __shared__ ulonglong2 xs[GM_ROWS][C / 4];   // 16 KB
    const int t    = threadIdx.x;
    const int base = blockIdx.x * GM_ROWS;
    const int rows = min(GM_ROWS, n - base);

    const ulonglong2* xg = (const ulonglong2*)(x + (size_t)base * C);
    for (int i = t; i < rows * (C / 4); i += 128)
        ((ulonglong2*)xs)[i] = xg[i];
    __syncthreads();

    unsigned long long acc[GM_ROWS];
#pragma unroll
    for (int r = 0; r < GM_ROWS; r++) acc[r] = 0ull;

#pragma unroll 4
    for (int k4 = 0; k4 < C / 4; k4++) {          // k4 covers k-steps 4k4..4k4+3
        unsigned long long wA = g_wt[(2 * k4)     * C + t];
        unsigned long long wB = g_wt[(2 * k4 + 1) * C + t];
#pragma unroll
        for (int r = 0; r < GM_ROWS; r++) {
            ulonglong2 xv = xs[r][k4];            // broadcast LDS.128
            asm("fma.rn.f32x2 %0, %1, %2, %0;" : "+l"(acc[r]) : "l"(xv.x), "l"(wA));
            asm("fma.rn.f32x2 %0, %1, %2, %0;" : "+l"(acc[r]) : "l"(xv.y), "l"(wB));
        }
    }

    for (int r = 0; r < rows; r++) {
        int row  = base + r;
        float lo = __uint_as_float((unsigned)(acc[r] & 0xffffffffull));
        float hi = __uint_as_float((unsigned)(acc[r] >> 32));
        g_hs[(size_t)row * C + t] = (lo + hi) * g_dinv[row];
    }
}

// ---------------------------------------------------------------------------
// 6) gather-reduce + finalize (fused): one warp per destination node.
//    lane l owns channels [4l, 4l+4). acc seeded with hs[v] (self loop).
//    out[v] = relu(dinv[v] * (hs[v] + sum_{neighbors} hs[row]) + b)
__global__ void __launch_bounds__(256) k_agg(float* __restrict__ out,
                                             const float* __restrict__ b, int n) {
    int warp = (blockIdx.x * blockDim.x + threadIdx.x) >> 5;
    if (warp >= n) return;
    const int lane = threadIdx.x & 31;
    const int v    = warp;
    const int beg  = g_off[v];
    const int cnt  = g_deg[v];

    float4 acc = *(const float4*)(g_hs + (size_t)v * C + lane * 4);  // self loop

    for (int base = 0; base < cnt; base += 32) {
        int idx = 0;
        if (base + lane < cnt) idx = g_csr[beg + base + lane];
        int m = min(32, cnt - base);
        for (int j = 0; j < m; j++) {
            int row  = __shfl_sync(0xffffffffu, idx, j);
            float4 h = *(const float4*)(g_hs + (size_t)row * C + lane * 4);
            acc.x += h.x; acc.y += h.y; acc.z += h.z; acc.w += h.w;
        }
    }

    const float  d  = g_dinv[v];
    const float4 bb = ((const float4*)b)[lane];
    float4 o;
    o.x = fmaxf(fmaf(acc.x, d, bb.x), 0.0f);
    o.y = fmaxf(fmaf(acc.y, d, bb.y), 0.0f);
    o.z = fmaxf(fmaf(acc.z, d, bb.z), 0.0f);
    o.w = fmaxf(fmaf(acc.w, d, bb.w), 0.0f);
    ((float4*)out)[(size_t)v * (C / 4) + lane] = o;
}

// ---------------------------------------------------------------------------
extern "C" void kernel_launch(void* const* d_in, const int* in_sizes, int n_in,
                              void* d_out, int out_size)
{
    const float* x  = (const float*)d_in[0];
    const void*  ei = d_in[1];                 // [2, E] int32 or int64 (detected)
    const float* W  = (const float*)d_in[2];
    const float* b  = (const float*)d_in[3];
    float*       out = (float*)d_out;

    const int n  = in_sizes[0] / C;
    const int E  = in_sizes[1] / 2;
    const int nb = (n + SCAN_B - 1) / SCAN_B;

    k_detect       <<<1, 1>>>((const unsigned*)ei);
    k_zero         <<<(n + 255) / 256, 256>>>(n);
    k_convert_count<<<(2 * E + 255) / 256, 256>>>(ei, E, n);
    k_scan1        <<<nb, SCAN_B>>>(n);
    k_scan2        <<<1, 1024>>>(nb);
    k_scan3        <<<nb, SCAN_B>>>(n);
    k_fill         <<<(E + 255) / 256, 256>>>(E, n);
    k_wt           <<<(64 * C + 255) / 256, 256>>>(W);
    k_gemm         <<<(n + GM_ROWS - 1) / GM_ROWS, 128>>>(x, n);
    k_agg          <<<(n * 32 + 255) / 256, 256>>>(out, b, n);
}

// round 11
// speedup vs baseline: 1.8894x; 1.0412x over previous
#include <cuda_runtime.h>

#define C      128
#define MAX_N  100000
#define MAX_E  1600000
#define SCAN_B 256

// Scratch (allocation-free rule: __device__ globals)
__device__ int   g_is64;
__device__ int   g_ei[2 * MAX_E];            // normalized int32 edge index
__device__ int   g_deg[MAX_N];               // edge-only in-degree (no self loop)
__device__ int   g_off[MAX_N];               // CSR start offsets (by target)
__device__ int   g_cur[MAX_N];               // fill cursors
__device__ int   g_csr[MAX_E];               // source node per CSR slot
__device__ int   g_bsum[(MAX_N + SCAN_B - 1) / SCAN_B + 1];  // block sums / prefixes
__device__ float g_dinv[MAX_N];              // rsqrt(deg+1)
__device__ float g_hs[(size_t)MAX_N * C];    // hs = x @ W   (UNSCALED now)
__device__ unsigned long long g_wt[64 * C];  // W as k-pair f32x2: (W[2k2][c], W[2k2+1][c])

// ---------------------------------------------------------------------------
// 0a) dtype detect: int64 values < 2^31 have zero odd 32-bit words (LE).
__global__ void k_detect(const unsigned* __restrict__ ei32) {
    int all0 = 1;
#pragma unroll 4
    for (int i = 0; i < 64; i++)
        if (ei32[2 * i + 1] != 0u) all0 = 0;
    g_is64 = all0;
}

// 0b) pre-pack W into k-pair f32x2 layout: g_wt[k2*C + c] = (W[2k2][c], W[2k2+1][c])
__global__ void k_wt(const float* __restrict__ W) {
    int i = blockIdx.x * blockDim.x + threadIdx.x;
    if (i >= 64 * C) return;
    int c = i & (C - 1), k2 = i >> 7;
    unsigned lo = __float_as_uint(W[(2 * k2)     * C + c]);
    unsigned hi = __float_as_uint(W[(2 * k2 + 1) * C + c]);
    g_wt[i] = ((unsigned long long)hi << 32) | lo;
}

// 0c) zero degrees
__global__ void k_zero(int n) {
    int i = blockIdx.x * blockDim.x + threadIdx.x;
    if (i < n) g_deg[i] = 0;
}

// ---------------------------------------------------------------------------
// 1) GEMM via packed fma.rn.f32x2: hs[row] = x[row] @ W  (no dinv — moved to agg).
//    Thread t = channel t; 32 rows per block. x-tile in shared as ulonglong2:
//    each 16B holds 2 pre-packed (k,k+1) f32x2 pairs -> zero pack instructions.
//    acc.lo sums even-k products, acc.hi odd-k; added in epilogue (exact fp32).
#define GM_ROWS 32
__global__ void __launch_bounds__(128) k_gemm(const float* __restrict__ x, int n) {
    __shared__ ulonglong2 xs[GM_ROWS][C / 4];   // 16 KB
    const int t    = threadIdx.x;
    const int base = blockIdx.x * GM_ROWS;
    const int rows = min(GM_ROWS, n - base);

    const ulonglong2* xg = (const ulonglong2*)(x + (size_t)base * C);
    for (int i = t; i < rows * (C / 4); i += 128)
        ((ulonglong2*)xs)[i] = xg[i];
    __syncthreads();

    unsigned long long acc[GM_ROWS];
#pragma unroll
    for (int r = 0; r < GM_ROWS; r++) acc[r] = 0ull;

#pragma unroll 4
    for (int k4 = 0; k4 < C / 4; k4++) {          // k4 covers k-steps 4k4..4k4+3
        unsigned long long wA = g_wt[(2 * k4)     * C + t];
        unsigned long long wB = g_wt[(2 * k4 + 1) * C + t];
#pragma unroll
        for (int r = 0; r < GM_ROWS; r++) {
            ulonglong2 xv = xs[r][k4];            // broadcast LDS.128
            asm("fma.rn.f32x2 %0, %1, %2, %0;" : "+l"(acc[r]) : "l"(xv.x), "l"(wA));
            asm("fma.rn.f32x2 %0, %1, %2, %0;" : "+l"(acc[r]) : "l"(xv.y), "l"(wB));
        }
    }

    for (int r = 0; r < rows; r++) {
        int row  = base + r;
        float lo = __uint_as_float((unsigned)(acc[r] & 0xffffffffull));
        float hi = __uint_as_float((unsigned)(acc[r] >> 32));
        g_hs[(size_t)row * C + t] = lo + hi;
    }
}

// ---------------------------------------------------------------------------
// 2) normalize edge index to int32 AND count in-degree (col half) in one pass
__global__ void k_convert_count(const void* __restrict__ ei, int E, int n) {
    int i = blockIdx.x * blockDim.x + threadIdx.x;
    if (i >= 2 * E) return;
    int v;
    if (g_is64) v = (int)((const long long*)ei)[i];
    else        v = ((const int*)ei)[i];
    g_ei[i] = v;
    if (i >= E && (unsigned)v < (unsigned)n) atomicAdd(&g_deg[v], 1);
}

// ---------------------------------------------------------------------------
// 3) multi-block exclusive scan of g_deg -> g_off (3 phases, all chip-wide)

__global__ void __launch_bounds__(SCAN_B) k_scan1(int n) {
    __shared__ int sh[SCAN_B];
    const int tid = threadIdx.x;
    const int i   = blockIdx.x * SCAN_B + tid;
    int d = (i < n) ? g_deg[i] : 0;
    sh[tid] = d;
    __syncthreads();
#pragma unroll
    for (int off = 1; off < SCAN_B; off <<= 1) {
        int v = (tid >= off) ? sh[tid - off] : 0;
        __syncthreads();
        sh[tid] += v;
        __syncthreads();
    }
    if (i < n) g_off[i] = sh[tid] - d;            // block-local exclusive
    if (tid == SCAN_B - 1) g_bsum[blockIdx.x] = sh[tid];
}

__global__ void __launch_bounds__(1024) k_scan2(int nb) {
    __shared__ int sh[1024];
    const int tid = threadIdx.x;
    int d = (tid < nb) ? g_bsum[tid] : 0;
    sh[tid] = d;
    __syncthreads();
#pragma unroll
    for (int off = 1; off < 1024; off <<= 1) {
        int v = (tid >= off) ? sh[tid - off] : 0;
        __syncthreads();
        sh[tid] += v;
        __syncthreads();
    }
    if (tid < nb) g_bsum[tid] = sh[tid] - d;      // exclusive block prefix
}

__global__ void __launch_bounds__(SCAN_B) k_scan3(int n) {
    const int i = blockIdx.x * SCAN_B + threadIdx.x;
    if (i >= n) return;
    int o = g_off[i] + g_bsum[blockIdx.x];
    g_off[i]  = o;
    g_cur[i]  = o;
    g_dinv[i] = rsqrtf((float)(g_deg[i] + 1));    // +1 = self loop
}

// ---------------------------------------------------------------------------
// 4) CSR fill: slot per edge via cursor atomics; store source node
__global__ void k_fill(int E, int n) {
    int i = blockIdx.x * blockDim.x + threadIdx.x;
    if (i >= E) return;
    unsigned row = (unsigned)g_ei[i];
    unsigned col = (unsigned)g_ei[E + i];
    if (row >= (unsigned)n || col >= (unsigned)n) return;
    int slot = atomicAdd(&g_cur[col], 1);
    g_csr[slot] = (int)row;
}

// ---------------------------------------------------------------------------
// 5) gather-reduce + finalize (fused): one warp per destination node.
//    lane l owns channels [4l, 4l+4). 4-edge unroll -> 4 LDG.128 in flight.
//    out[v] = relu(dinv[v] * (dinv[v]*h[v] + sum_e dinv[row]*h[row]) + b)
__global__ void __launch_bounds__(256) k_agg(float* __restrict__ out,
                                             const float* __restrict__ b, int n) {
    int warp = (blockIdx.x * blockDim.x + threadIdx.x) >> 5;
    if (warp >= n) return;
    const int lane = threadIdx.x & 31;
    const int v    = warp;
    const int beg  = g_off[v];
    const int cnt  = g_deg[v];
    const float dv = g_dinv[v];
    const float4* __restrict__ hp = (const float4*)g_hs;

    float4 acc = hp[(size_t)v * 32 + lane];       // self loop: dinv[v]*h[v]
    acc.x *= dv; acc.y *= dv; acc.z *= dv; acc.w *= dv;

    for (int base = 0; base < cnt; base += 32) {
        int   idx = 0;
        float dd  = 0.0f;
        if (base + lane < cnt) {
            idx = g_csr[beg + base + lane];
            dd  = g_dinv[idx];                    // prefetch norm beside index
        }
        const int m = min(32, cnt - base);
        int j = 0;
        for (; j + 4 <= m; j += 4) {
            int   r0 = __shfl_sync(~0u, idx, j),     r1 = __shfl_sync(~0u, idx, j + 1);
            int   r2 = __shfl_sync(~0u, idx, j + 2), r3 = __shfl_sync(~0u, idx, j + 3);
            float d0 = __shfl_sync(~0u, dd, j),      d1 = __shfl_sync(~0u, dd, j + 1);
            float d2 = __shfl_sync(~0u, dd, j + 2),  d3 = __shfl_sync(~0u, dd, j + 3);
            float4 h0 = hp[(size_t)r0 * 32 + lane];  // 4 independent LDG.128
            float4 h1 = hp[(size_t)r1 * 32 + lane];
            float4 h2 = hp[(size_t)r2 * 32 + lane];
            float4 h3 = hp[(size_t)r3 * 32 + lane];
            acc.x = fmaf(h0.x, d0, fmaf(h1.x, d1, fmaf(h2.x, d2, fmaf(h3.x, d3, acc.x))));
            acc.y = fmaf(h0.y, d0, fmaf(h1.y, d1, fmaf(h2.y, d2, fmaf(h3.y, d3, acc.y))));
            acc.z = fmaf(h0.z, d0, fmaf(h1.z, d1, fmaf(h2.z, d2, fmaf(h3.z, d3, acc.z))));
            acc.w = fmaf(h0.w, d0, fmaf(h1.w, d1, fmaf(h2.w, d2, fmaf(h3.w, d3, acc.w))));
        }
        for (; j < m; j++) {
            int   r = __shfl_sync(~0u, idx, j);
            float d = __shfl_sync(~0u, dd, j);
            float4 h = hp[(size_t)r * 32 + lane];
            acc.x = fmaf(h.x, d, acc.x);
            acc.y = fmaf(h.y, d, acc.y);
            acc.z = fmaf(h.z, d, acc.z);
            acc.w = fmaf(h.w, d, acc.w);
        }
    }

    const float4 bb = ((const float4*)b)[lane];
    float4 o;
    o.x = fmaxf(fmaf(acc.x, dv, bb.x), 0.0f);
    o.y = fmaxf(fmaf(acc.y, dv, bb.y), 0.0f);
    o.z = fmaxf(fmaf(acc.z, dv, bb.z), 0.0f);
    o.w = fmaxf(fmaf(acc.w, dv, bb.w), 0.0f);
    ((float4*)out)[(size_t)v * (C / 4) + lane] = o;
}

// ---------------------------------------------------------------------------
extern "C" void kernel_launch(void* const* d_in, const int* in_sizes, int n_in,
                              void* d_out, int out_size)
{
    const float* x  = (const float*)d_in[0];
    const void*  ei = d_in[1];                 // [2, E] int32 or int64 (detected)
    const float* W  = (const float*)d_in[2];
    const float* b  = (const float*)d_in[3];
    float*       out = (float*)d_out;

    const int n  = in_sizes[0] / C;
    const int E  = in_sizes[1] / 2;
    const int nb = (n + SCAN_B - 1) / SCAN_B;

    k_detect       <<<1, 1>>>((const unsigned*)ei);                 // 1
    k_wt           <<<(64 * C + 255) / 256, 256>>>(W);              // 2
    k_zero         <<<(n + 255) / 256, 256>>>(n);                   // 3
    k_gemm         <<<(n + GM_ROWS - 1) / GM_ROWS, 128>>>(x, n);    // 4 <- profiled
    k_convert_count<<<(2 * E + 255) / 256, 256>>>(ei, E, n);        // 5
    k_scan1        <<<nb, SCAN_B>>>(n);                             // 6
    k_scan2        <<<1, 1024>>>(nb);                               // 7
    k_scan3        <<<nb, SCAN_B>>>(n);                             // 8
    k_fill         <<<(E + 255) / 256, 256>>>(E, n);                // 9
    k_agg          <<<(n * 32 + 255) / 256, 256>>>(out, b, n);      // 10
}

// round 14
// speedup vs baseline: 2.3070x; 1.2210x over previous
#include <cuda_runtime.h>

#define C      128
#define MAX_N  100000
#define MAX_E  1600000
#define SCAN_B 256

// Scratch (allocation-free rule: __device__ globals)
__device__ int   g_is64;
__device__ int   g_ei[2 * MAX_E];            // normalized int32 edge index
__device__ int   g_deg[MAX_N];               // edge-only in-degree (no self loop)
__device__ int   g_off[MAX_N];               // CSR start offsets (by target)
__device__ int   g_cur[MAX_N];               // fill cursors
__device__ int   g_csr[MAX_E];               // source node per CSR slot
__device__ int   g_bsum[(MAX_N + SCAN_B - 1) / SCAN_B + 1];  // block sums / prefixes
__device__ float g_dinv[MAX_N];              // rsqrt(deg+1)
__device__ float g_hs[(size_t)MAX_N * C];    // hs = x @ W (unscaled)
__device__ unsigned long long g_wt[64 * C];  // W as k-pair f32x2: (W[2k2][c], W[2k2+1][c])

// ---------------------------------------------------------------------------
// 0a) dtype detect: int64 values < 2^31 have zero odd 32-bit words (LE).
__global__ void k_detect(const unsigned* __restrict__ ei32) {
    int all0 = 1;
#pragma unroll 4
    for (int i = 0; i < 64; i++)
        if (ei32[2 * i + 1] != 0u) all0 = 0;
    g_is64 = all0;
}

// 0b) pre-pack W into k-pair f32x2 layout: g_wt[k2*C + c] = (W[2k2][c], W[2k2+1][c])
__global__ void k_wt(const float* __restrict__ W) {
    int i = blockIdx.x * blockDim.x + threadIdx.x;
    if (i >= 64 * C) return;
    int c = i & (C - 1), k2 = i >> 7;
    unsigned lo = __float_as_uint(W[(2 * k2)     * C + c]);
    unsigned hi = __float_as_uint(W[(2 * k2 + 1) * C + c]);
    g_wt[i] = ((unsigned long long)hi << 32) | lo;
}

// 0c) zero degrees
__global__ void k_zero(int n) {
    int i = blockIdx.x * blockDim.x + threadIdx.x;
    if (i < n) g_deg[i] = 0;
}

// ---------------------------------------------------------------------------
// 1) GEMM, register-blocked outer product with packed fma.rn.f32x2.
//    Block 256 = (tx 32, ty 8). Tile = 64 rows x 128 channels.
//    Thread: 8 rows (ty + 8r) x 4 channels (tx + 32i). acc.lo = even-k sum,
//    acc.hi = odd-k sum, added in epilogue (exact fp32).
//    Per k2: 4 LDG.64 (W pairs, L1-hot) + 8 broadcast LDS.64 + 32 FFMA2.
#define GM_TILE_R 64
__global__ void __launch_bounds__(256) k_gemm(const float* __restrict__ x, int n) {
    __shared__ unsigned long long xs[GM_TILE_R][C / 2];   // 32 KB, [row][k2]
    const int t    = threadIdx.x;
    const int tx   = t & 31;
    const int ty   = t >> 5;
    const int base = blockIdx.x * GM_TILE_R;
    const int rows = min(GM_TILE_R, n - base);

    // cooperative x-tile load (ulonglong2 = 2 k-pairs), zero-pad tail rows
    {
        const ulonglong2* xg  = (const ulonglong2*)(x + (size_t)base * C);
        ulonglong2*       xsv = (ulonglong2*)xs;
        for (int i = t; i < GM_TILE_R * (C / 4); i += 256) {
            int r = i >> 5;
            ulonglong2 v;
            if (r < rows) v = xg[i];
            else          { v.x = 0ull; v.y = 0ull; }
            xsv[i] = v;
        }
    }
    __syncthreads();

    unsigned long long acc[8][4];
#pragma unroll
    for (int r = 0; r < 8; r++)
#pragma unroll
        for (int i = 0; i < 4; i++) acc[r][i] = 0ull;

#pragma unroll 2
    for (int k2 = 0; k2 < C / 2; k2++) {
        unsigned long long w0 = __ldg(&g_wt[k2 * C + tx]);
        unsigned long long w1 = __ldg(&g_wt[k2 * C + tx + 32]);
        unsigned long long w2 = __ldg(&g_wt[k2 * C + tx + 64]);
        unsigned long long w3 = __ldg(&g_wt[k2 * C + tx + 96]);
#pragma unroll
        for (int r = 0; r < 8; r++) {
            unsigned long long xv = xs[ty + 8 * r][k2];   // broadcast LDS.64
            asm("fma.rn.f32x2 %0, %1, %2, %0;" : "+l"(acc[r][0]) : "l"(xv), "l"(w0));
            asm("fma.rn.f32x2 %0, %1, %2, %0;" : "+l"(acc[r][1]) : "l"(xv), "l"(w1));
            asm("fma.rn.f32x2 %0, %1, %2, %0;" : "+l"(acc[r][2]) : "l"(xv), "l"(w2));
            asm("fma.rn.f32x2 %0, %1, %2, %0;" : "+l"(acc[r][3]) : "l"(xv), "l"(w3));
        }
    }

#pragma unroll
    for (int r = 0; r < 8; r++) {
        int row = base + ty + 8 * r;
        if (row < n) {
            float* dst = g_hs + (size_t)row * C;
#pragma unroll
            for (int i = 0; i < 4; i++) {
                float lo = __uint_as_float((unsigned)(acc[r][i] & 0xffffffffull));
                float hi = __uint_as_float((unsigned)(acc[r][i] >> 32));
                dst[tx + 32 * i] = lo + hi;       // coalesced 128B per (r,i)
            }
        }
    }
}

// ---------------------------------------------------------------------------
// 2) normalize edge index to int32 AND count in-degree (col half) in one pass
__global__ void k_convert_count(const void* __restrict__ ei, int E, int n) {
    int i = blockIdx.x * blockDim.x + threadIdx.x;
    if (i >= 2 * E) return;
    int v;
    if (g_is64) v = (int)((const long long*)ei)[i];
    else        v = ((const int*)ei)[i];
    g_ei[i] = v;
    if (i >= E && (unsigned)v < (unsigned)n) atomicAdd(&g_deg[v], 1);
}

// ---------------------------------------------------------------------------
// 3) multi-block exclusive scan of g_deg -> g_off (3 phases, all chip-wide)

__global__ void __launch_bounds__(SCAN_B) k_scan1(int n) {
    __shared__ int sh[SCAN_B];
    const int tid = threadIdx.x;
    const int i   = blockIdx.x * SCAN_B + tid;
    int d = (i < n) ? g_deg[i] : 0;
    sh[tid] = d;
    __syncthreads();
#pragma unroll
    for (int off = 1; off < SCAN_B; off <<= 1) {
        int v = (tid >= off) ? sh[tid - off] : 0;
        __syncthreads();
        sh[tid] += v;
        __syncthreads();
    }
    if (i < n) g_off[i] = sh[tid] - d;            // block-local exclusive
    if (tid == SCAN_B - 1) g_bsum[blockIdx.x] = sh[tid];
}

__global__ void __launch_bounds__(1024) k_scan2(int nb) {
    __shared__ int sh[1024];
    const int tid = threadIdx.x;
    int d = (tid < nb) ? g_bsum[tid] : 0;
    sh[tid] = d;
    __syncthreads();
#pragma unroll
    for (int off = 1; off < 1024; off <<= 1) {
        int v = (tid >= off) ? sh[tid - off] : 0;
        __syncthreads();
        sh[tid] += v;
        __syncthreads();
    }
    if (tid < nb) g_bsum[tid] = sh[tid] - d;      // exclusive block prefix
}

__global__ void __launch_bounds__(SCAN_B) k_scan3(int n) {
    const int i = blockIdx.x * SCAN_B + threadIdx.x;
    if (i >= n) return;
    int o = g_off[i] + g_bsum[blockIdx.x];
    g_off[i]  = o;
    g_cur[i]  = o;
    g_dinv[i] = rsqrtf((float)(g_deg[i] + 1));    // +1 = self loop
}

// ---------------------------------------------------------------------------
// 4) CSR fill: slot per edge via cursor atomics; store source node
__global__ void k_fill(int E, int n) {
    int i = blockIdx.x * blockDim.x + threadIdx.x;
    if (i >= E) return;
    unsigned row = (unsigned)g_ei[i];
    unsigned col = (unsigned)g_ei[E + i];
    if (row >= (unsigned)n || col >= (unsigned)n) return;
    int slot = atomicAdd(&g_cur[col], 1);
    g_csr[slot] = (int)row;
}

// ---------------------------------------------------------------------------
// 5) gather-reduce + finalize (fused): one warp per destination node.
//    lane l owns channels [4l, 4l+4). 4-edge unroll -> 4 LDG.128 in flight.
//    out[v] = relu(dinv[v] * (dinv[v]*h[v] + sum_e dinv[row]*h[row]) + b)
__global__ void __launch_bounds__(256) k_agg(float* __restrict__ out,
                                             const float* __restrict__ b, int n) {
    int warp = (blockIdx.x * blockDim.x + threadIdx.x) >> 5;
    if (warp >= n) return;
    const int lane = threadIdx.x & 31;
    const int v    = warp;
    const int beg  = g_off[v];
    const int cnt  = g_deg[v];
    const float dv = g_dinv[v];
    const float4* __restrict__ hp = (const float4*)g_hs;

    float4 acc = hp[(size_t)v * 32 + lane];       // self loop: dinv[v]*h[v]
    acc.x *= dv; acc.y *= dv; acc.z *= dv; acc.w *= dv;

    for (int base = 0; base < cnt; base += 32) {
        int   idx = 0;
        float dd  = 0.0f;
        if (base + lane < cnt) {
            idx = g_csr[beg + base + lane];
            dd  = g_dinv[idx];                    // prefetch norm beside index
        }
        const int m = min(32, cnt - base);
        int j = 0;
        for (; j + 4 <= m; j += 4) {
            int   r0 = __shfl_sync(~0u, idx, j),     r1 = __shfl_sync(~0u, idx, j + 1);
            int   r2 = __shfl_sync(~0u, idx, j + 2), r3 = __shfl_sync(~0u, idx, j + 3);
            float d0 = __shfl_sync(~0u, dd, j),      d1 = __shfl_sync(~0u, dd, j + 1);
            float d2 = __shfl_sync(~0u, dd, j + 2),  d3 = __shfl_sync(~0u, dd, j + 3);
            float4 h0 = hp[(size_t)r0 * 32 + lane];  // 4 independent LDG.128
            float4 h1 = hp[(size_t)r1 * 32 + lane];
            float4 h2 = hp[(size_t)r2 * 32 + lane];
            float4 h3 = hp[(size_t)r3 * 32 + lane];
            acc.x = fmaf(h0.x, d0, fmaf(h1.x, d1, fmaf(h2.x, d2, fmaf(h3.x, d3, acc.x))));
            acc.y = fmaf(h0.y, d0, fmaf(h1.y, d1, fmaf(h2.y, d2, fmaf(h3.y, d3, acc.y))));
            acc.z = fmaf(h0.z, d0, fmaf(h1.z, d1, fmaf(h2.z, d2, fmaf(h3.z, d3, acc.z))));
            acc.w = fmaf(h0.w, d0, fmaf(h1.w, d1, fmaf(h2.w, d2, fmaf(h3.w, d3, acc.w))));
        }
        for (; j < m; j++) {
            int   r = __shfl_sync(~0u, idx, j);
            float d = __shfl_sync(~0u, dd, j);
            float4 h = hp[(size_t)r * 32 + lane];
            acc.x = fmaf(h.x, d, acc.x);
            acc.y = fmaf(h.y, d, acc.y);
            acc.z = fmaf(h.z, d, acc.z);
            acc.w = fmaf(h.w, d, acc.w);
        }
    }

    const float4 bb = ((const float4*)b)[lane];
    float4 o;
    o.x = fmaxf(fmaf(acc.x, dv, bb.x), 0.0f);
    o.y = fmaxf(fmaf(acc.y, dv, bb.y), 0.0f);
    o.z = fmaxf(fmaf(acc.z, dv, bb.z), 0.0f);
    o.w = fmaxf(fmaf(acc.w, dv, bb.w), 0.0f);
    ((float4*)out)[(size_t)v * (C / 4) + lane] = o;
}

// ---------------------------------------------------------------------------
extern "C" void kernel_launch(void* const* d_in, const int* in_sizes, int n_in,
                              void* d_out, int out_size)
{
    const float* x  = (const float*)d_in[0];
    const void*  ei = d_in[1];                 // [2, E] int32 or int64 (detected)
    const float* W  = (const float*)d_in[2];
    const float* b  = (const float*)d_in[3];
    float*       out = (float*)d_out;

    const int n  = in_sizes[0] / C;
    const int E  = in_sizes[1] / 2;
    const int nb = (n + SCAN_B - 1) / SCAN_B;

    k_detect       <<<1, 1>>>((const unsigned*)ei);                     // 1
    k_wt           <<<(64 * C + 255) / 256, 256>>>(W);                  // 2
    k_zero         <<<(n + 255) / 256, 256>>>(n);                       // 3
    k_gemm         <<<(n + GM_TILE_R - 1) / GM_TILE_R, 256>>>(x, n);    // 4 <- profiled
    k_convert_count<<<(2 * E + 255) / 256, 256>>>(ei, E, n);            // 5
    k_scan1        <<<nb, SCAN_B>>>(n);                                 // 6
    k_scan2        <<<1, 1024>>>(nb);                                   // 7
    k_scan3        <<<nb, SCAN_B>>>(n);                                 // 8
    k_fill         <<<(E + 255) / 256, 256>>>(E, n);                    // 9
    k_agg          <<<(n * 32 + 255) / 256, 256>>>(out, b, n);          // 10
}